// round 16
// baseline (speedup 1.0000x reference)
#include <cuda_runtime.h>
#include <cuda_fp16.h>
#include <math.h>
#include <stdint.h>

#define S_      300
#define B_      128
#define INTOK   64
#define H_      1024
#define FINAL_  64
#define NLAYERS 3
#define NHEAD_  4
#define HD_     256
#define M_      (S_*B_)      // 38400 rows

#define BM 128
#define BN 128
#define BK 64
#define BKP 72               // halfs per smem row (144B stride, conflict-free ldmatrix)
#define STAGES 3
#define NTHREADS 128         // 4 warps, 64x64 warp tiles, 2 CTAs/SM (2*110.6KB smem)

// ---------------- scratch (static device arrays; no cudaMalloc) -------
__device__ __half h_b  [(size_t)M_ * H_];       // half gemm delta (for residual)
__device__ __half h_x  [(size_t)M_ * H_];       // half residual stream
__device__ __half h_qkv[(size_t)M_ * 3 * H_];   // half qkv
__device__ __half h_a  [(size_t)M_ * H_];       // half attn-out / relu-out
__device__ __half h_src[(size_t)M_ * INTOK];    // half src

// half weights, concatenated
#define OFF_ENC 0
#define OFF_IPW (OFF_ENC + (size_t)H_*INTOK)
#define OFF_OPW (OFF_IPW + (size_t)NLAYERS*3*H_*H_)
#define OFF_L1W (OFF_OPW + (size_t)NLAYERS*H_*H_)
#define OFF_L2W (OFF_L1W + (size_t)NLAYERS*H_*H_)
#define OFF_FC  (OFF_L2W + (size_t)NLAYERS*H_*H_)
#define W_TOTAL (OFF_FC + (size_t)FINAL_*H_)
__device__ __half h_w[W_TOTAL];

// ---------------- small PTX helpers ----------------
__device__ __forceinline__ uint32_t smem_u32(const void* p) {
    uint32_t a;
    asm("{ .reg .u64 t; cvta.to.shared.u64 t, %1; cvt.u32.u64 %0, t; }" : "=r"(a) : "l"(p));
    return a;
}
__device__ __forceinline__ void cp_async16(uint32_t s, const void* g) {
    asm volatile("cp.async.cg.shared.global [%0], [%1], 16;" :: "r"(s), "l"(g));
}
#define CP_COMMIT() asm volatile("cp.async.commit_group;" ::: "memory")
#define CP_WAIT(n)  asm volatile("cp.async.wait_group %0;" :: "n"(n) : "memory")

__device__ __forceinline__ void ldsm_x4(uint32_t* r, uint32_t addr) {
    asm volatile("ldmatrix.sync.aligned.m8n8.x4.shared.b16 {%0,%1,%2,%3}, [%4];"
                 : "=r"(r[0]), "=r"(r[1]), "=r"(r[2]), "=r"(r[3]) : "r"(addr));
}
__device__ __forceinline__ void mma_f16(float* d, const uint32_t* a, const uint32_t* b) {
    asm volatile(
        "mma.sync.aligned.m16n8k16.row.col.f32.f16.f16.f32 "
        "{%0,%1,%2,%3},{%4,%5,%6,%7},{%8,%9},{%0,%1,%2,%3};"
        : "+f"(d[0]), "+f"(d[1]), "+f"(d[2]), "+f"(d[3])
        : "r"(a[0]), "r"(a[1]), "r"(a[2]), "r"(a[3]), "r"(b[0]), "r"(b[1]));
}

// ---------------- merged f32 -> f16 convert kernel (7 segments) -------------
__global__ void __launch_bounds__(256) f2h_all_kernel(
    const float4* __restrict__ i0, __half2* __restrict__ o0, int n0,
    const float4* __restrict__ i1, __half2* __restrict__ o1, int n1,
    const float4* __restrict__ i2, __half2* __restrict__ o2, int n2,
    const float4* __restrict__ i3, __half2* __restrict__ o3, int n3,
    const float4* __restrict__ i4, __half2* __restrict__ o4, int n4,
    const float4* __restrict__ i5, __half2* __restrict__ o5, int n5,
    const float4* __restrict__ i6, __half2* __restrict__ o6, int n6)
{
    int i = blockIdx.x * 256 + threadIdx.x;
    const float4* in; __half2* out;
    if (i < n0)      { in = i0; out = o0; }
    else { i -= n0;
    if (i < n1)      { in = i1; out = o1; }
    else { i -= n1;
    if (i < n2)      { in = i2; out = o2; }
    else { i -= n2;
    if (i < n3)      { in = i3; out = o3; }
    else { i -= n3;
    if (i < n4)      { in = i4; out = o4; }
    else { i -= n4;
    if (i < n5)      { in = i5; out = o5; }
    else { i -= n5;
    if (i < n6)      { in = i6; out = o6; }
    else return; }}}}}}
    float4 v = in[i];
    out[2 * i]     = __floats2half2_rn(v.x, v.y);
    out[2 * i + 1] = __floats2half2_rn(v.z, v.w);
}

// ======================= fp16 mma.sync GEMM =======================
// C[M,N] = A[M,K] @ W[N,K]^T + bias (+ReLU). A, W half; fp32 accum.
// 128x128 CTA tile, 4 warps of 64x64, BK=64, 3-stage cp.async pipeline.
// OMODE: 0 = fp32 C only; 2 = half Ch only.
template<int RELU, int OMODE>
__global__ void __launch_bounds__(NTHREADS, 2) tc_gemm(
    const __half* __restrict__ A, const __half* __restrict__ W,
    const float* __restrict__ bias, float* __restrict__ C, __half* __restrict__ Ch,
    int M, int N, int K)
{
    extern __shared__ __half sm[];
    __half* sA = sm;                           // [STAGES][BM*BKP]
    __half* sB = sm + STAGES * BM * BKP;       // [STAGES][BN*BKP]

    const int tid = threadIdx.x;
    const int bm = blockIdx.y, bn = blockIdx.x;
    const int rowA0 = bm * BM, rowB0 = bn * BN;

    if (rowB0 + BN > N) {
        uint32_t* z = reinterpret_cast<uint32_t*>(sB);
        for (int i = tid; i < STAGES * BN * BKP / 2; i += NTHREADS) z[i] = 0u;
        __syncthreads();
    }

    const int w = tid >> 5, lane = tid & 31;
    const int g = lane >> 2, t = lane & 3;
    const int wm = (w >> 1) * 64;      // warp grid 2 (M) x 2 (N)
    const int wn = (w & 1) * 64;

    float acc[4][8][4];
    #pragma unroll
    for (int i = 0; i < 4; i++)
        #pragma unroll
        for (int j = 0; j < 8; j++)
            #pragma unroll
            for (int q = 0; q < 4; q++) acc[i][j][q] = 0.f;

    // stage: 128 rows x 64 halfs = 1024 16B-chunks per operand; 8/thread each
    auto load_stage = [&](int buf, int k0) {
        __half* dA = sA + buf * BM * BKP;
        __half* dB = sB + buf * BN * BKP;
        #pragma unroll
        for (int i = 0; i < 8; i++) {
            int idx = tid + i * NTHREADS;
            int row = idx >> 3, ch = (idx & 7) << 3;
            cp_async16(smem_u32(dA + row * BKP + ch),
                       A + (size_t)(rowA0 + row) * K + k0 + ch);
            if (rowB0 + row < N)
                cp_async16(smem_u32(dB + row * BKP + ch),
                           W + (size_t)(rowB0 + row) * K + k0 + ch);
        }
        CP_COMMIT();
    };

    const int nk = K / BK;
    load_stage(0, 0);
    if (nk > 1) load_stage(1, BK);

    const int lm = lane >> 3;            // matrix idx 0..3
    const int lr = lane & 7;
    const int a_radd = (lm & 1) * 8, a_cadd = (lm >> 1) * 8;
    const int b_radd = (lm >> 1) * 8, b_cadd = (lm & 1) * 8;

    int buf = 0;
    for (int kt = 0; kt < nk; kt++) {
        if (kt + 2 < nk) {
            load_stage((kt + 2) % STAGES, (kt + 2) * BK);
            CP_WAIT(2);
        } else if (kt + 1 < nk) {
            CP_WAIT(1);
        } else {
            CP_WAIT(0);
        }
        __syncthreads();

        const __half* cA = sA + buf * BM * BKP;
        const __half* cB = sB + buf * BN * BKP;

        #pragma unroll
        for (int kk = 0; kk < 4; kk++) {
            uint32_t af[4][4], bf[8][2];
            #pragma unroll
            for (int mi = 0; mi < 4; mi++) {
                int r = wm + mi * 16 + a_radd + lr;
                ldsm_x4(af[mi], smem_u32(cA + r * BKP + kk * 16 + a_cadd));
            }
            #pragma unroll
            for (int p = 0; p < 4; p++) {
                uint32_t rr[4];
                int r = wn + p * 16 + b_radd + lr;
                ldsm_x4(rr, smem_u32(cB + r * BKP + kk * 16 + b_cadd));
                bf[2 * p][0] = rr[0]; bf[2 * p][1] = rr[1];
                bf[2 * p + 1][0] = rr[2]; bf[2 * p + 1][1] = rr[3];
            }
            #pragma unroll
            for (int mi = 0; mi < 4; mi++)
                #pragma unroll
                for (int ni = 0; ni < 8; ni++)
                    mma_f16(acc[mi][ni], af[mi], bf[ni]);
        }
        __syncthreads();
        buf = (buf + 1) % STAGES;
    }

    // ---- epilogue ----
    #pragma unroll
    for (int mi = 0; mi < 4; mi++) {
        #pragma unroll
        for (int ni = 0; ni < 8; ni++) {
            int col = rowB0 + wn + ni * 8 + 2 * t;
            if (col < N) {
                float b0 = __ldg(bias + col), b1 = __ldg(bias + col + 1);
                #pragma unroll
                for (int half_ = 0; half_ < 2; half_++) {
                    int row = rowA0 + wm + mi * 16 + g + half_ * 8;
                    float v0 = acc[mi][ni][half_ * 2 + 0] + b0;
                    float v1 = acc[mi][ni][half_ * 2 + 1] + b1;
                    if (RELU) { v0 = fmaxf(v0, 0.f); v1 = fmaxf(v1, 0.f); }
                    size_t off = (size_t)row * N + col;
                    if (OMODE != 2)
                        *reinterpret_cast<float2*>(C + off) = make_float2(v0, v1);
                    else
                        *reinterpret_cast<__half2*>(Ch + off) = __floats2half2_rn(v0, v1);
                }
            }
        }
    }
}

// ---------------- banded attention: 1 warp per (s, b, head), half2 loads ----
__global__ void __launch_bounds__(256) attn_kernel(
    const __half* __restrict__ qkv, __half* __restrict__ o)
{
    int gw   = (blockIdx.x * blockDim.x + threadIdx.x) >> 5;
    int lane = threadIdx.x & 31;
    if (gw >= M_ * NHEAD_) return;
    int h  = gw & (NHEAD_ - 1);
    int sb = gw >> 2;
    int s  = sb / B_;
    int b  = sb - s * B_;
    const float scale = 0.0625f;

    const __half2* qr = reinterpret_cast<const __half2*>(
        qkv + (size_t)sb * (3 * H_) + h * HD_);
    float2 q[4];
    #pragma unroll
    for (int i = 0; i < 4; i++) q[i] = __half22float2(qr[lane + 32 * i]);

    float sc[3];
    const int j0 = s - 2;
    #pragma unroll
    for (int jj = 0; jj < 3; jj++) {
        int j = j0 + jj;
        float p = -INFINITY;
        if (j >= 0) {
            const __half2* kr = reinterpret_cast<const __half2*>(
                qkv + (size_t)(j * B_ + b) * (3 * H_) + H_ + h * HD_);
            float d = 0.f;
            #pragma unroll
            for (int i = 0; i < 4; i++) {
                float2 k2 = __half22float2(kr[lane + 32 * i]);
                d += q[i].x * k2.x + q[i].y * k2.y;
            }
            #pragma unroll
            for (int off = 16; off; off >>= 1) d += __shfl_xor_sync(0xffffffffu, d, off);
            p = d * scale;
        }
        sc[jj] = p;
    }
    float m = fmaxf(sc[0], fmaxf(sc[1], sc[2]));
    float e[3];
    float esum = 0.f;
    #pragma unroll
    for (int jj = 0; jj < 3; jj++) { e[jj] = __expf(sc[jj] - m); esum += e[jj]; }
    float inv = 1.f / esum;

    float2 accv[4];
    #pragma unroll
    for (int i = 0; i < 4; i++) accv[i] = make_float2(0.f, 0.f);
    #pragma unroll
    for (int jj = 0; jj < 3; jj++) {
        int j = j0 + jj;
        if (j < 0) continue;
        float wgt = e[jj] * inv;
        const __half2* vr = reinterpret_cast<const __half2*>(
            qkv + (size_t)(j * B_ + b) * (3 * H_) + 2 * H_ + h * HD_);
        #pragma unroll
        for (int i = 0; i < 4; i++) {
            float2 v2 = __half22float2(vr[lane + 32 * i]);
            accv[i].x += wgt * v2.x;
            accv[i].y += wgt * v2.y;
        }
    }
    __half2* orow = reinterpret_cast<__half2*>(o + (size_t)sb * H_ + h * HD_);
    #pragma unroll
    for (int i = 0; i < 4; i++)
        orow[lane + 32 * i] = __floats2half2_rn(accv[i].x, accv[i].y);
}

// ---------------- residual add + LayerNorm (all-half streams, fp32 math) ----
__device__ __forceinline__ float block_sum256(float s) {
    __shared__ float red[8];
    #pragma unroll
    for (int o = 16; o; o >>= 1) s += __shfl_xor_sync(0xffffffffu, s, o);
    int wid = threadIdx.x >> 5, lane = threadIdx.x & 31;
    if (lane == 0) red[wid] = s;
    __syncthreads();
    float t = (wid == 0 && lane < 8) ? red[lane] : 0.f;
    if (wid == 0) {
        #pragma unroll
        for (int o = 4; o; o >>= 1) t += __shfl_xor_sync(0xffffffffu, t, o);
        if (lane == 0) red[0] = t;
    }
    __syncthreads();
    float r = red[0];
    __syncthreads();
    return r;
}

__global__ void __launch_bounds__(256) add_ln_kernel(
    __half* __restrict__ xh, const __half* __restrict__ d,
    const float* __restrict__ g, const float* __restrict__ b)
{
    int row = blockIdx.x;
    int tid = threadIdx.x;
    __half2* xrow = reinterpret_cast<__half2*>(xh + (size_t)row * H_);
    const __half2* drow = reinterpret_cast<const __half2*>(d + (size_t)row * H_);
    const float4* g4 = reinterpret_cast<const float4*>(g);
    const float4* b4 = reinterpret_cast<const float4*>(b);

    float2 x0 = __half22float2(xrow[2 * tid]);
    float2 x1 = __half22float2(xrow[2 * tid + 1]);
    float2 d0 = __half22float2(drow[2 * tid]);
    float2 d1 = __half22float2(drow[2 * tid + 1]);
    float4 v = make_float4(x0.x + d0.x, x0.y + d0.y, x1.x + d1.x, x1.y + d1.y);
    float s = v.x + v.y + v.z + v.w;
    float mean = block_sum256(s) * (1.f / H_);
    float t0 = v.x - mean, t1 = v.y - mean, t2 = v.z - mean, t3 = v.w - mean;
    float vs = t0 * t0 + t1 * t1 + t2 * t2 + t3 * t3;
    float var = block_sum256(vs) * (1.f / H_);
    float rstd = rsqrtf(var + 1e-5f);

    float4 gv = __ldg(g4 + tid), bv = __ldg(b4 + tid);
    float y0 = t0 * rstd * gv.x + bv.x;
    float y1 = t1 * rstd * gv.y + bv.y;
    float y2 = t2 * rstd * gv.z + bv.z;
    float y3 = t3 * rstd * gv.w + bv.w;
    xrow[2 * tid]     = __floats2half2_rn(y0, y1);
    xrow[2 * tid + 1] = __floats2half2_rn(y2, y3);
}

// ---------------- host orchestration ----------------
static void* symaddr(const void* sym) {
    void* p = nullptr;
    cudaGetSymbolAddress(&p, sym);
    return p;
}

#define GEMM_SMEM (STAGES * (BM + BN) * BKP * 2)   // 110592 bytes

extern "C" void kernel_launch(void* const* d_in, const int* in_sizes, int n_in,
                              void* d_out, int out_size) {
    const float* src        = (const float*)d_in[0];
    const float* enc_w      = (const float*)d_in[1];
    const float* enc_b      = (const float*)d_in[2];
    const float* in_proj_w  = (const float*)d_in[3];
    const float* in_proj_b  = (const float*)d_in[4];
    const float* out_proj_w = (const float*)d_in[5];
    const float* out_proj_b = (const float*)d_in[6];
    const float* ln1_g      = (const float*)d_in[7];
    const float* ln1_b      = (const float*)d_in[8];
    const float* lin1_w     = (const float*)d_in[9];
    const float* lin1_b     = (const float*)d_in[10];
    const float* lin2_w     = (const float*)d_in[11];
    const float* lin2_b     = (const float*)d_in[12];
    const float* ln2_g      = (const float*)d_in[13];
    const float* ln2_b      = (const float*)d_in[14];
    const float* fc_w       = (const float*)d_in[15];
    const float* fc_b       = (const float*)d_in[16];
    float* out = (float*)d_out;

    __half* bh   = (__half*)symaddr(h_b);
    __half* xh   = (__half*)symaddr(h_x);
    __half* qkvh = (__half*)symaddr(h_qkv);
    __half* ah   = (__half*)symaddr(h_a);
    __half* srch = (__half*)symaddr(h_src);
    __half* wbuf = (__half*)symaddr(h_w);

    cudaFuncSetAttribute(tc_gemm<0,0>, cudaFuncAttributeMaxDynamicSharedMemorySize, GEMM_SMEM);
    cudaFuncSetAttribute(tc_gemm<0,2>, cudaFuncAttributeMaxDynamicSharedMemorySize, GEMM_SMEM);
    cudaFuncSetAttribute(tc_gemm<1,2>, cudaFuncAttributeMaxDynamicSharedMemorySize, GEMM_SMEM);

    // convert all weights + src to half in ONE launch
    {
        int n0 = (int)(((size_t)NLAYERS * 3 * H_ * H_) / 4);   // in_proj
        int n1 = (int)(((size_t)NLAYERS * H_ * H_) / 4);       // out_proj
        int n2 = n1;                                           // lin1
        int n3 = n1;                                           // lin2
        int n4 = (int)(((size_t)M_ * INTOK) / 4);              // src
        int n5 = (int)(((size_t)H_ * INTOK) / 4);              // enc
        int n6 = (int)(((size_t)FINAL_ * H_) / 4);             // fc
        int total = n0 + n1 + n2 + n3 + n4 + n5 + n6;
        f2h_all_kernel<<<(total + 255) / 256, 256>>>(
            (const float4*)in_proj_w,  (__half2*)(wbuf + OFF_IPW), n0,
            (const float4*)out_proj_w, (__half2*)(wbuf + OFF_OPW), n1,
            (const float4*)lin1_w,     (__half2*)(wbuf + OFF_L1W), n2,
            (const float4*)lin2_w,     (__half2*)(wbuf + OFF_L2W), n3,
            (const float4*)src,        (__half2*)srch,             n4,
            (const float4*)enc_w,      (__half2*)(wbuf + OFF_ENC), n5,
            (const float4*)fc_w,       (__half2*)(wbuf + OFF_FC),  n6);
    }

    const dim3 blk(NTHREADS);
    const dim3 grid_h (H_ / BN,       M_ / BM);    // 8 x 300
    const dim3 grid_3h(3 * H_ / BN,   M_ / BM);    // 24 x 300
    const dim3 grid_f (1,             M_ / BM);
    const int attn_blocks = (M_ * NHEAD_) / 8;

    // encoder: xh = half(src @ enc_w^T + enc_b)   (K=64 -> nk=1)
    tc_gemm<0,2><<<grid_h, blk, GEMM_SMEM>>>(srch, wbuf + OFF_ENC, enc_b, nullptr,
                                             xh, M_, H_, INTOK);

    for (int l = 0; l < NLAYERS; l++) {
        const __half* ipw = wbuf + OFF_IPW + (size_t)l * 3 * H_ * H_;
        const __half* opw = wbuf + OFF_OPW + (size_t)l * H_ * H_;
        const __half* l1w = wbuf + OFF_L1W + (size_t)l * H_ * H_;
        const __half* l2w = wbuf + OFF_L2W + (size_t)l * H_ * H_;
        const float* ipb = in_proj_b  + (size_t)l * 3 * H_;
        const float* opb = out_proj_b + (size_t)l * H_;
        const float* l1b = lin1_b     + (size_t)l * H_;
        const float* l2b = lin2_b     + (size_t)l * H_;

        tc_gemm<0,2><<<grid_3h, blk, GEMM_SMEM>>>(xh, ipw, ipb, nullptr, qkvh,
                                                  M_, 3 * H_, H_);
        attn_kernel<<<attn_blocks, 256>>>(qkvh, ah);
        tc_gemm<0,2><<<grid_h, blk, GEMM_SMEM>>>(ah, opw, opb, nullptr, bh,
                                                 M_, H_, H_);
        add_ln_kernel<<<M_, 256>>>(xh, bh,
                                   ln1_g + (size_t)l * H_, ln1_b + (size_t)l * H_);
        tc_gemm<1,2><<<grid_h, blk, GEMM_SMEM>>>(xh, l1w, l1b, nullptr, ah,
                                                 M_, H_, H_);
        tc_gemm<0,2><<<grid_h, blk, GEMM_SMEM>>>(ah, l2w, l2b, nullptr, bh,
                                                 M_, H_, H_);
        add_ln_kernel<<<M_, 256>>>(xh, bh,
                                   ln2_g + (size_t)l * H_, ln2_b + (size_t)l * H_);
    }

    // final: out = xh @ fc_w^T + fc_b (fp32 output)
    tc_gemm<0,0><<<grid_f, blk, GEMM_SMEM>>>(xh, wbuf + OFF_FC, fc_b, out, nullptr,
                                             M_, FINAL_, H_);
}

// round 17
// speedup vs baseline: 1.0695x; 1.0695x over previous
#include <cuda_runtime.h>
#include <cuda_fp16.h>
#include <math.h>
#include <stdint.h>

#define S_      300
#define B_      128
#define INTOK   64
#define H_      1024
#define FINAL_  64
#define NLAYERS 3
#define NHEAD_  4
#define HD_     256
#define M_      (S_*B_)      // 38400 rows

#define BM 128
#define BN 128
#define BK 32
#define BKP 40               // halfs per smem row (80B stride, conflict-free ldmatrix)
#define STAGES 3
#define NTHREADS 128         // 4 warps, 64x64 warp tiles, 2 CTAs/SM

// ---------------- scratch (static device arrays; no cudaMalloc) -------
__device__ __half h_b  [(size_t)M_ * H_];       // half gemm delta (for residual)
__device__ __half h_x  [(size_t)M_ * H_];       // half residual stream
__device__ __half h_qkv[(size_t)M_ * 3 * H_];   // half qkv
__device__ __half h_a  [(size_t)M_ * H_];       // half attn-out / relu-out
__device__ __half h_src[(size_t)M_ * INTOK];    // half src

// half weights, concatenated
#define OFF_ENC 0
#define OFF_IPW (OFF_ENC + (size_t)H_*INTOK)
#define OFF_OPW (OFF_IPW + (size_t)NLAYERS*3*H_*H_)
#define OFF_L1W (OFF_OPW + (size_t)NLAYERS*H_*H_)
#define OFF_L2W (OFF_L1W + (size_t)NLAYERS*H_*H_)
#define OFF_FC  (OFF_L2W + (size_t)NLAYERS*H_*H_)
#define W_TOTAL (OFF_FC + (size_t)FINAL_*H_)
__device__ __half h_w[W_TOTAL];

// ---------------- small PTX helpers ----------------
__device__ __forceinline__ uint32_t smem_u32(const void* p) {
    uint32_t a;
    asm("{ .reg .u64 t; cvta.to.shared.u64 t, %1; cvt.u32.u64 %0, t; }" : "=r"(a) : "l"(p));
    return a;
}
__device__ __forceinline__ void cp_async16(uint32_t s, const void* g) {
    asm volatile("cp.async.cg.shared.global [%0], [%1], 16;" :: "r"(s), "l"(g));
}
#define CP_COMMIT() asm volatile("cp.async.commit_group;" ::: "memory")
#define CP_WAIT(n)  asm volatile("cp.async.wait_group %0;" :: "n"(n) : "memory")

__device__ __forceinline__ void ldsm_x4(uint32_t* r, uint32_t addr) {
    asm volatile("ldmatrix.sync.aligned.m8n8.x4.shared.b16 {%0,%1,%2,%3}, [%4];"
                 : "=r"(r[0]), "=r"(r[1]), "=r"(r[2]), "=r"(r[3]) : "r"(addr));
}
__device__ __forceinline__ void mma_f16(float* d, const uint32_t* a, const uint32_t* b) {
    asm volatile(
        "mma.sync.aligned.m16n8k16.row.col.f32.f16.f16.f32 "
        "{%0,%1,%2,%3},{%4,%5,%6,%7},{%8,%9},{%0,%1,%2,%3};"
        : "+f"(d[0]), "+f"(d[1]), "+f"(d[2]), "+f"(d[3])
        : "r"(a[0]), "r"(a[1]), "r"(a[2]), "r"(a[3]), "r"(b[0]), "r"(b[1]));
}

// ---------------- merged f32 -> f16 convert kernel (7 segments) -------------
__global__ void __launch_bounds__(256) f2h_all_kernel(
    const float4* __restrict__ i0, __half2* __restrict__ o0, int n0,
    const float4* __restrict__ i1, __half2* __restrict__ o1, int n1,
    const float4* __restrict__ i2, __half2* __restrict__ o2, int n2,
    const float4* __restrict__ i3, __half2* __restrict__ o3, int n3,
    const float4* __restrict__ i4, __half2* __restrict__ o4, int n4,
    const float4* __restrict__ i5, __half2* __restrict__ o5, int n5,
    const float4* __restrict__ i6, __half2* __restrict__ o6, int n6)
{
    int i = blockIdx.x * 256 + threadIdx.x;
    const float4* in; __half2* out;
    if (i < n0)      { in = i0; out = o0; }
    else { i -= n0;
    if (i < n1)      { in = i1; out = o1; }
    else { i -= n1;
    if (i < n2)      { in = i2; out = o2; }
    else { i -= n2;
    if (i < n3)      { in = i3; out = o3; }
    else { i -= n3;
    if (i < n4)      { in = i4; out = o4; }
    else { i -= n4;
    if (i < n5)      { in = i5; out = o5; }
    else { i -= n5;
    if (i < n6)      { in = i6; out = o6; }
    else return; }}}}}}
    float4 v = in[i];
    out[2 * i]     = __floats2half2_rn(v.x, v.y);
    out[2 * i + 1] = __floats2half2_rn(v.z, v.w);
}

// ======================= fp16 mma.sync GEMM =======================
// C[M,N] = A[M,K] @ W[N,K]^T + bias (+ReLU). A, W half; fp32 accum.
// 128x128 CTA tile, 4 warps of 64x64, BK=32, 3-stage cp.async pipeline (R11).
// OMODE: 0 = fp32 C only; 2 = half Ch only.
template<int RELU, int OMODE>
__global__ void __launch_bounds__(NTHREADS, 2) tc_gemm(
    const __half* __restrict__ A, const __half* __restrict__ W,
    const float* __restrict__ bias, float* __restrict__ C, __half* __restrict__ Ch,
    int M, int N, int K)
{
    extern __shared__ __half sm[];
    __half* sA = sm;                           // [STAGES][BM*BKP]
    __half* sB = sm + STAGES * BM * BKP;       // [STAGES][BN*BKP]

    const int tid = threadIdx.x;
    const int bm = blockIdx.y, bn = blockIdx.x;
    const int rowA0 = bm * BM, rowB0 = bn * BN;

    if (rowB0 + BN > N) {
        uint32_t* z = reinterpret_cast<uint32_t*>(sB);
        for (int i = tid; i < STAGES * BN * BKP / 2; i += NTHREADS) z[i] = 0u;
        __syncthreads();
    }

    const int w = tid >> 5, lane = tid & 31;
    const int g = lane >> 2, t = lane & 3;
    const int wm = (w >> 1) * 64;      // warp grid 2 (M) x 2 (N)
    const int wn = (w & 1) * 64;

    float acc[4][8][4];
    #pragma unroll
    for (int i = 0; i < 4; i++)
        #pragma unroll
        for (int j = 0; j < 8; j++)
            #pragma unroll
            for (int q = 0; q < 4; q++) acc[i][j][q] = 0.f;

    // stage: 128 rows x 32 halfs = 512 16B-chunks per operand; 4/thread each
    auto load_stage = [&](int buf, int k0) {
        __half* dA = sA + buf * BM * BKP;
        __half* dB = sB + buf * BN * BKP;
        #pragma unroll
        for (int i = 0; i < 4; i++) {
            int idx = tid + i * NTHREADS;
            int row = idx >> 2, ch = (idx & 3) << 3;
            cp_async16(smem_u32(dA + row * BKP + ch),
                       A + (size_t)(rowA0 + row) * K + k0 + ch);
            if (rowB0 + row < N)
                cp_async16(smem_u32(dB + row * BKP + ch),
                           W + (size_t)(rowB0 + row) * K + k0 + ch);
        }
        CP_COMMIT();
    };

    const int nk = K / BK;
    load_stage(0, 0);
    if (nk > 1) load_stage(1, BK);

    const int lm = lane >> 3;            // matrix idx 0..3
    const int lr = lane & 7;
    const int a_radd = (lm & 1) * 8, a_cadd = (lm >> 1) * 8;
    const int b_radd = (lm >> 1) * 8, b_cadd = (lm & 1) * 8;

    int buf = 0;
    for (int kt = 0; kt < nk; kt++) {
        if (kt + 2 < nk) {
            load_stage((kt + 2) % STAGES, (kt + 2) * BK);
            CP_WAIT(2);
        } else if (kt + 1 < nk) {
            CP_WAIT(1);
        } else {
            CP_WAIT(0);
        }
        __syncthreads();

        const __half* cA = sA + buf * BM * BKP;
        const __half* cB = sB + buf * BN * BKP;

        #pragma unroll
        for (int kk = 0; kk < 2; kk++) {
            uint32_t af[4][4], bf[8][2];
            #pragma unroll
            for (int mi = 0; mi < 4; mi++) {
                int r = wm + mi * 16 + a_radd + lr;
                ldsm_x4(af[mi], smem_u32(cA + r * BKP + kk * 16 + a_cadd));
            }
            #pragma unroll
            for (int p = 0; p < 4; p++) {
                uint32_t rr[4];
                int r = wn + p * 16 + b_radd + lr;
                ldsm_x4(rr, smem_u32(cB + r * BKP + kk * 16 + b_cadd));
                bf[2 * p][0] = rr[0]; bf[2 * p][1] = rr[1];
                bf[2 * p + 1][0] = rr[2]; bf[2 * p + 1][1] = rr[3];
            }
            #pragma unroll
            for (int mi = 0; mi < 4; mi++)
                #pragma unroll
                for (int ni = 0; ni < 8; ni++)
                    mma_f16(acc[mi][ni], af[mi], bf[ni]);
        }
        __syncthreads();
        buf = (buf + 1) % STAGES;
    }

    // ---- epilogue ----
    #pragma unroll
    for (int mi = 0; mi < 4; mi++) {
        #pragma unroll
        for (int ni = 0; ni < 8; ni++) {
            int col = rowB0 + wn + ni * 8 + 2 * t;
            if (col < N) {
                float b0 = __ldg(bias + col), b1 = __ldg(bias + col + 1);
                #pragma unroll
                for (int half_ = 0; half_ < 2; half_++) {
                    int row = rowA0 + wm + mi * 16 + g + half_ * 8;
                    float v0 = acc[mi][ni][half_ * 2 + 0] + b0;
                    float v1 = acc[mi][ni][half_ * 2 + 1] + b1;
                    if (RELU) { v0 = fmaxf(v0, 0.f); v1 = fmaxf(v1, 0.f); }
                    size_t off = (size_t)row * N + col;
                    if (OMODE != 2)
                        *reinterpret_cast<float2*>(C + off) = make_float2(v0, v1);
                    else
                        *reinterpret_cast<__half2*>(Ch + off) = __floats2half2_rn(v0, v1);
                }
            }
        }
    }
}

// ---------------- banded attention: 1 warp per (s, b, head), half2 loads ----
__global__ void __launch_bounds__(256) attn_kernel(
    const __half* __restrict__ qkv, __half* __restrict__ o)
{
    int gw   = (blockIdx.x * blockDim.x + threadIdx.x) >> 5;
    int lane = threadIdx.x & 31;
    if (gw >= M_ * NHEAD_) return;
    int h  = gw & (NHEAD_ - 1);
    int sb = gw >> 2;
    int s  = sb / B_;
    int b  = sb - s * B_;
    const float scale = 0.0625f;

    const __half2* qr = reinterpret_cast<const __half2*>(
        qkv + (size_t)sb * (3 * H_) + h * HD_);
    float2 q[4];
    #pragma unroll
    for (int i = 0; i < 4; i++) q[i] = __half22float2(qr[lane + 32 * i]);

    float sc[3];
    const int j0 = s - 2;
    #pragma unroll
    for (int jj = 0; jj < 3; jj++) {
        int j = j0 + jj;
        float p = -INFINITY;
        if (j >= 0) {
            const __half2* kr = reinterpret_cast<const __half2*>(
                qkv + (size_t)(j * B_ + b) * (3 * H_) + H_ + h * HD_);
            float d = 0.f;
            #pragma unroll
            for (int i = 0; i < 4; i++) {
                float2 k2 = __half22float2(kr[lane + 32 * i]);
                d += q[i].x * k2.x + q[i].y * k2.y;
            }
            #pragma unroll
            for (int off = 16; off; off >>= 1) d += __shfl_xor_sync(0xffffffffu, d, off);
            p = d * scale;
        }
        sc[jj] = p;
    }
    float m = fmaxf(sc[0], fmaxf(sc[1], sc[2]));
    float e[3];
    float esum = 0.f;
    #pragma unroll
    for (int jj = 0; jj < 3; jj++) { e[jj] = __expf(sc[jj] - m); esum += e[jj]; }
    float inv = 1.f / esum;

    float2 accv[4];
    #pragma unroll
    for (int i = 0; i < 4; i++) accv[i] = make_float2(0.f, 0.f);
    #pragma unroll
    for (int jj = 0; jj < 3; jj++) {
        int j = j0 + jj;
        if (j < 0) continue;
        float wgt = e[jj] * inv;
        const __half2* vr = reinterpret_cast<const __half2*>(
            qkv + (size_t)(j * B_ + b) * (3 * H_) + 2 * H_ + h * HD_);
        #pragma unroll
        for (int i = 0; i < 4; i++) {
            float2 v2 = __half22float2(vr[lane + 32 * i]);
            accv[i].x += wgt * v2.x;
            accv[i].y += wgt * v2.y;
        }
    }
    __half2* orow = reinterpret_cast<__half2*>(o + (size_t)sb * H_ + h * HD_);
    #pragma unroll
    for (int i = 0; i < 4; i++)
        orow[lane + 32 * i] = __floats2half2_rn(accv[i].x, accv[i].y);
}

// ---------------- residual add + LayerNorm (all-half streams, fp32 math) ----
__device__ __forceinline__ float block_sum256(float s) {
    __shared__ float red[8];
    #pragma unroll
    for (int o = 16; o; o >>= 1) s += __shfl_xor_sync(0xffffffffu, s, o);
    int wid = threadIdx.x >> 5, lane = threadIdx.x & 31;
    if (lane == 0) red[wid] = s;
    __syncthreads();
    float t = (wid == 0 && lane < 8) ? red[lane] : 0.f;
    if (wid == 0) {
        #pragma unroll
        for (int o = 4; o; o >>= 1) t += __shfl_xor_sync(0xffffffffu, t, o);
        if (lane == 0) red[0] = t;
    }
    __syncthreads();
    float r = red[0];
    __syncthreads();
    return r;
}

__global__ void __launch_bounds__(256) add_ln_kernel(
    __half* __restrict__ xh, const __half* __restrict__ d,
    const float* __restrict__ g, const float* __restrict__ b)
{
    int row = blockIdx.x;
    int tid = threadIdx.x;
    __half2* xrow = reinterpret_cast<__half2*>(xh + (size_t)row * H_);
    const __half2* drow = reinterpret_cast<const __half2*>(d + (size_t)row * H_);
    const float4* g4 = reinterpret_cast<const float4*>(g);
    const float4* b4 = reinterpret_cast<const float4*>(b);

    float2 x0 = __half22float2(xrow[2 * tid]);
    float2 x1 = __half22float2(xrow[2 * tid + 1]);
    float2 d0 = __half22float2(drow[2 * tid]);
    float2 d1 = __half22float2(drow[2 * tid + 1]);
    float4 v = make_float4(x0.x + d0.x, x0.y + d0.y, x1.x + d1.x, x1.y + d1.y);
    float s = v.x + v.y + v.z + v.w;
    float mean = block_sum256(s) * (1.f / H_);
    float t0 = v.x - mean, t1 = v.y - mean, t2 = v.z - mean, t3 = v.w - mean;
    float vs = t0 * t0 + t1 * t1 + t2 * t2 + t3 * t3;
    float var = block_sum256(vs) * (1.f / H_);
    float rstd = rsqrtf(var + 1e-5f);

    float4 gv = __ldg(g4 + tid), bv = __ldg(b4 + tid);
    float y0 = t0 * rstd * gv.x + bv.x;
    float y1 = t1 * rstd * gv.y + bv.y;
    float y2 = t2 * rstd * gv.z + bv.z;
    float y3 = t3 * rstd * gv.w + bv.w;
    xrow[2 * tid]     = __floats2half2_rn(y0, y1);
    xrow[2 * tid + 1] = __floats2half2_rn(y2, y3);
}

// ---------------- host orchestration ----------------
static void* symaddr(const void* sym) {
    void* p = nullptr;
    cudaGetSymbolAddress(&p, sym);
    return p;
}

#define GEMM_SMEM (STAGES * (BM + BN) * BKP * 2)   // 61440 bytes

extern "C" void kernel_launch(void* const* d_in, const int* in_sizes, int n_in,
                              void* d_out, int out_size) {
    const float* src        = (const float*)d_in[0];
    const float* enc_w      = (const float*)d_in[1];
    const float* enc_b      = (const float*)d_in[2];
    const float* in_proj_w  = (const float*)d_in[3];
    const float* in_proj_b  = (const float*)d_in[4];
    const float* out_proj_w = (const float*)d_in[5];
    const float* out_proj_b = (const float*)d_in[6];
    const float* ln1_g      = (const float*)d_in[7];
    const float* ln1_b      = (const float*)d_in[8];
    const float* lin1_w     = (const float*)d_in[9];
    const float* lin1_b     = (const float*)d_in[10];
    const float* lin2_w     = (const float*)d_in[11];
    const float* lin2_b     = (const float*)d_in[12];
    const float* ln2_g      = (const float*)d_in[13];
    const float* ln2_b      = (const float*)d_in[14];
    const float* fc_w       = (const float*)d_in[15];
    const float* fc_b       = (const float*)d_in[16];
    float* out = (float*)d_out;

    __half* bh   = (__half*)symaddr(h_b);
    __half* xh   = (__half*)symaddr(h_x);
    __half* qkvh = (__half*)symaddr(h_qkv);
    __half* ah   = (__half*)symaddr(h_a);
    __half* srch = (__half*)symaddr(h_src);
    __half* wbuf = (__half*)symaddr(h_w);

    cudaFuncSetAttribute(tc_gemm<0,0>, cudaFuncAttributeMaxDynamicSharedMemorySize, GEMM_SMEM);
    cudaFuncSetAttribute(tc_gemm<0,2>, cudaFuncAttributeMaxDynamicSharedMemorySize, GEMM_SMEM);
    cudaFuncSetAttribute(tc_gemm<1,2>, cudaFuncAttributeMaxDynamicSharedMemorySize, GEMM_SMEM);

    // convert all weights + src to half in ONE launch
    {
        int n0 = (int)(((size_t)NLAYERS * 3 * H_ * H_) / 4);   // in_proj
        int n1 = (int)(((size_t)NLAYERS * H_ * H_) / 4);       // out_proj
        int n2 = n1;                                           // lin1
        int n3 = n1;                                           // lin2
        int n4 = (int)(((size_t)M_ * INTOK) / 4);              // src
        int n5 = (int)(((size_t)H_ * INTOK) / 4);              // enc
        int n6 = (int)(((size_t)FINAL_ * H_) / 4);             // fc
        int total = n0 + n1 + n2 + n3 + n4 + n5 + n6;
        f2h_all_kernel<<<(total + 255) / 256, 256>>>(
            (const float4*)in_proj_w,  (__half2*)(wbuf + OFF_IPW), n0,
            (const float4*)out_proj_w, (__half2*)(wbuf + OFF_OPW), n1,
            (const float4*)lin1_w,     (__half2*)(wbuf + OFF_L1W), n2,
            (const float4*)lin2_w,     (__half2*)(wbuf + OFF_L2W), n3,
            (const float4*)src,        (__half2*)srch,             n4,
            (const float4*)enc_w,      (__half2*)(wbuf + OFF_ENC), n5,
            (const float4*)fc_w,       (__half2*)(wbuf + OFF_FC),  n6);
    }

    const dim3 blk(NTHREADS);
    const dim3 grid_h (H_ / BN,       M_ / BM);    // 8 x 300
    const dim3 grid_3h(3 * H_ / BN,   M_ / BM);    // 24 x 300
    const dim3 grid_f (1,             M_ / BM);
    const int attn_blocks = (M_ * NHEAD_) / 8;

    // encoder: xh = half(src @ enc_w^T + enc_b)
    tc_gemm<0,2><<<grid_h, blk, GEMM_SMEM>>>(srch, wbuf + OFF_ENC, enc_b, nullptr,
                                             xh, M_, H_, INTOK);

    for (int l = 0; l < NLAYERS; l++) {
        const __half* ipw = wbuf + OFF_IPW + (size_t)l * 3 * H_ * H_;
        const __half* opw = wbuf + OFF_OPW + (size_t)l * H_ * H_;
        const __half* l1w = wbuf + OFF_L1W + (size_t)l * H_ * H_;
        const __half* l2w = wbuf + OFF_L2W + (size_t)l * H_ * H_;
        const float* ipb = in_proj_b  + (size_t)l * 3 * H_;
        const float* opb = out_proj_b + (size_t)l * H_;
        const float* l1b = lin1_b     + (size_t)l * H_;
        const float* l2b = lin2_b     + (size_t)l * H_;

        tc_gemm<0,2><<<grid_3h, blk, GEMM_SMEM>>>(xh, ipw, ipb, nullptr, qkvh,
                                                  M_, 3 * H_, H_);
        attn_kernel<<<attn_blocks, 256>>>(qkvh, ah);
        tc_gemm<0,2><<<grid_h, blk, GEMM_SMEM>>>(ah, opw, opb, nullptr, bh,
                                                 M_, H_, H_);
        add_ln_kernel<<<M_, 256>>>(xh, bh,
                                   ln1_g + (size_t)l * H_, ln1_b + (size_t)l * H_);
        tc_gemm<1,2><<<grid_h, blk, GEMM_SMEM>>>(xh, l1w, l1b, nullptr, ah,
                                                 M_, H_, H_);
        tc_gemm<0,2><<<grid_h, blk, GEMM_SMEM>>>(ah, l2w, l2b, nullptr, bh,
                                                 M_, H_, H_);
        add_ln_kernel<<<M_, 256>>>(xh, bh,
                                   ln2_g + (size_t)l * H_, ln2_b + (size_t)l * H_);
    }

    // final: out = xh @ fc_w^T + fc_b (fp32 output)
    tc_gemm<0,0><<<grid_f, blk, GEMM_SMEM>>>(xh, wbuf + OFF_FC, fc_b, out, nullptr,
                                             M_, FINAL_, H_);
}